// round 12
// baseline (speedup 1.0000x reference)
#include <cuda_runtime.h>
#include <cstdint>

#define N_NODES 50000
#define N_EDGES 800000
#define E_TOT   850000          // edges + self loops
#define IN_CH   64
#define HEADS   8
#define OUT_CH  16
#define HID     128
#define N_GRAPHS 500
#define NEG_SLOPE 0.2f

#define SCAN_CHUNK 512
#define SCAN_NB    ((N_NODES + SCAN_CHUNK - 1) / SCAN_CHUNK)   // 98

typedef unsigned long long ull;

// ---------------- f32x2 packed helpers (sm_100+; ptxas never auto-emits FFMA2) ----
__device__ __forceinline__ ull pk2(float lo, float hi) {
    ull r; asm("mov.b64 %0, {%1, %2};" : "=l"(r) : "f"(lo), "f"(hi)); return r;
}
__device__ __forceinline__ void up2(ull v, float& lo, float& hi) {
    asm("mov.b64 {%0, %1}, %2;" : "=f"(lo), "=f"(hi) : "l"(v));
}
__device__ __forceinline__ ull add2(ull a, ull b) {
    ull d; asm("add.rn.f32x2 %0, %1, %2;" : "=l"(d) : "l"(a), "l"(b)); return d;
}
__device__ __forceinline__ ull mul2(ull a, ull b) {
    ull d; asm("mul.rn.f32x2 %0, %1, %2;" : "=l"(d) : "l"(a), "l"(b)); return d;
}
__device__ __forceinline__ ull fma2_(ull a, ull b, ull c) {
    ull d; asm("fma.rn.f32x2 %0, %1, %2, %3;" : "=l"(d) : "l"(a), "l"(b), "l"(c)); return d;
}
__device__ __forceinline__ ull abs2(ull a) {
    ull d; asm("and.b64 %0, %1, 0x7FFFFFFF7FFFFFFF;" : "=l"(d) : "l"(a)); return d;
}

// ---------------- scratch (static device globals) ---------------------------------
__device__ __align__(16) float g_xl[(size_t)N_NODES * HID];     // x@Wl (no bias)
__device__ __align__(16) float g_xr[(size_t)N_NODES * HID];     // x@Wr (no bias)
__device__ __align__(16) float g_xres[(size_t)N_NODES * HID];   // x@Wres (no bias)
__device__ int   g_cnt[N_NODES];          // in-degree histogram
__device__ int   g_off[N_NODES + 1];      // CSR row pointers
__device__ int   g_cur[N_NODES];          // scatter cursors
__device__ int   g_bsum[SCAN_NB];         // scan block sums
__device__ int   g_psrc[E_TOT];           // dst-sorted source ids
__device__ float g_gsum[N_GRAPHS * OUT_CH];
__device__ float g_gcnt[N_GRAPHS];
__device__ int   g_flags[2];   // [0]: edge_index is int64, [1]: batch is int64

// ---------------- init + dtype detection (merged) ---------------------------------
// int64 values < 2^31 stored little-endian -> every odd int32 word is 0.
__global__ void k_init(const int* __restrict__ ei, const int* __restrict__ batch) {
    const int i = blockIdx.x * blockDim.x + threadIdx.x;
    if (i == 0) {
        int acc = 0;
#pragma unroll 1
        for (int j = 0; j < 64; j++) acc |= ei[2 * j + 1];
        g_flags[0] = (acc == 0) ? 1 : 0;
        int acc2 = 0;
#pragma unroll 1
        for (int j = 0; j < 64; j++) acc2 |= batch[2001 + 2 * j];
        g_flags[1] = (acc2 == 0) ? 1 : 0;
    }
    if (i < N_NODES) g_cnt[i] = 0;
    if (i < N_GRAPHS * OUT_CH) g_gsum[i] = 0.f;
    if (i < N_GRAPHS) g_gcnt[i] = 0.f;
}

// ---------------- edge index helpers ----------------------------------------------
__device__ __forceinline__ int edge_dst(const int* __restrict__ ei, int e, int is64) {
    if (e >= N_EDGES) return e - N_EDGES;
    return is64 ? ei[2 * (N_EDGES + e)] : ei[N_EDGES + e];
}
__device__ __forceinline__ int edge_src(const int* __restrict__ ei, int e, int is64) {
    if (e >= N_EDGES) return e - N_EDGES;
    return is64 ? ei[2 * e] : ei[e];
}

// ---------------- counting sort: histogram ----------------------------------------
__global__ void k_hist(const int* __restrict__ ei) {
    const int e = blockIdx.x * blockDim.x + threadIdx.x;
    if (e >= E_TOT) return;
    const int dst = edge_dst(ei, e, g_flags[0]);
    atomicAdd(&g_cnt[dst], 1);
}

// ---------------- scan stage 1: per-chunk exclusive scan + chunk totals -----------
__global__ void k_scan1() {
    const int i = blockIdx.x * SCAN_CHUNK + threadIdx.x;
    const int lane = threadIdx.x & 31, wid = threadIdx.x >> 5;
    int c = (i < N_NODES) ? g_cnt[i] : 0;
    int v = c;
#pragma unroll
    for (int d = 1; d < 32; d <<= 1) {
        int t = __shfl_up_sync(0xffffffffu, v, d);
        if (lane >= d) v += t;
    }
    __shared__ int wsum[16];
    if (lane == 31) wsum[wid] = v;
    __syncthreads();
    if (wid == 0) {
        int w = (lane < 16) ? wsum[lane] : 0;
#pragma unroll
        for (int d = 1; d < 16; d <<= 1) {
            int t = __shfl_up_sync(0xffffffffu, w, d);
            if (lane >= d) w += t;
        }
        if (lane < 16) wsum[lane] = w;
    }
    __syncthreads();
    const int base = wid ? wsum[wid - 1] : 0;
    const int incl = v + base;
    if (i < N_NODES) g_off[i] = incl - c;     // chunk-local exclusive
    if (threadIdx.x == SCAN_CHUNK - 1) g_bsum[blockIdx.x] = incl;
}

// ---------------- fused node GEMMs (FFMA2, column-pair packing) -------------------
// f32x2 lanes = COLUMN PAIRS. Weights load directly as LDG.64 (no pack ALU);
// x values are pre-duplicated (v,v) in smem so the inner loop is LDS.128 + FFMA2.
// 256 threads, 32-node tile: thread = column-pair (t&63) x 8 nodes ((t>>6)*8).
// Per 2 k-steps: 48 FFMA2 + 6 LDG.64 + 8 LDS.128 -> ~72% FMA issue share.
__global__ void __launch_bounds__(256) k_gemm(const float* __restrict__ x,
                       const float* __restrict__ Wl,
                       const float* __restrict__ Wr,
                       const float* __restrict__ Wres) {
    __shared__ __align__(16) ull sx2[32][IN_CH];    // 16KB, (v,v) duplicated
    const int nb = blockIdx.x * 32;
    const int t  = threadIdx.x;                     // 0..255
    for (int i = t; i < 32 * IN_CH; i += 256) {
        const int n = i >> 6, k = i & 63;
        const float v = (nb + n < N_NODES) ? x[(size_t)(nb + n) * IN_CH + k] : 0.f;
        sx2[n][k] = pk2(v, v);
    }
    __syncthreads();

    const int cp = (t & 63) * 2;      // column pair base (0..126)
    const int g  = (t >> 6) * 8;      // node group base (0,8,16,24)

    ull accl[8], accr[8], accs[8];
#pragma unroll
    for (int p = 0; p < 8; p++) { accl[p] = 0ULL; accr[p] = 0ULL; accs[p] = 0ULL; }

#pragma unroll 2
    for (int k = 0; k < IN_CH; k += 2) {
        const ull wl0 = *reinterpret_cast<const ull*>(Wl   + (k    ) * HID + cp);
        const ull wr0 = *reinterpret_cast<const ull*>(Wr   + (k    ) * HID + cp);
        const ull ws0 = *reinterpret_cast<const ull*>(Wres + (k    ) * HID + cp);
        const ull wl1 = *reinterpret_cast<const ull*>(Wl   + (k + 1) * HID + cp);
        const ull wr1 = *reinterpret_cast<const ull*>(Wr   + (k + 1) * HID + cp);
        const ull ws1 = *reinterpret_cast<const ull*>(Wres + (k + 1) * HID + cp);
#pragma unroll
        for (int p = 0; p < 8; p++) {
            const ulonglong2 xv2 = *reinterpret_cast<const ulonglong2*>(&sx2[g + p][k]);
            accl[p] = fma2_(xv2.x, wl0, accl[p]);
            accr[p] = fma2_(xv2.x, wr0, accr[p]);
            accs[p] = fma2_(xv2.x, ws0, accs[p]);
            accl[p] = fma2_(xv2.y, wl1, accl[p]);
            accr[p] = fma2_(xv2.y, wr1, accr[p]);
            accs[p] = fma2_(xv2.y, ws1, accs[p]);
        }
    }
#pragma unroll
    for (int p = 0; p < 8; p++) {
        const int n = nb + g + p;
        if (n < N_NODES) {
            const size_t o = (size_t)n * HID + cp;
            *reinterpret_cast<ull*>(g_xl   + o) = accl[p];
            *reinterpret_cast<ull*>(g_xr   + o) = accr[p];
            *reinterpret_cast<ull*>(g_xres + o) = accs[p];
        }
    }
}

// ---------------- scan stage 2: exclusive scan of chunk totals --------------------
__global__ void k_scan2() {
    const int lane = threadIdx.x & 31, wid = threadIdx.x >> 5;
    const int b = threadIdx.x;
    int c = (b < SCAN_NB) ? g_bsum[b] : 0;
    int v = c;
#pragma unroll
    for (int d = 1; d < 32; d <<= 1) {
        int t = __shfl_up_sync(0xffffffffu, v, d);
        if (lane >= d) v += t;
    }
    __shared__ int wsum[4];
    if (lane == 31) wsum[wid] = v;
    __syncthreads();
    int base = 0;
    for (int w = 0; w < wid; w++) base += wsum[w];
    if (b < SCAN_NB) g_bsum[b] = v + base - c;   // exclusive
    if (b == 0) g_off[N_NODES] = E_TOT;
}

// ---------------- scan stage 3: add chunk offsets, init cursors -------------------
__global__ void k_scan3() {
    const int i = blockIdx.x * blockDim.x + threadIdx.x;
    if (i >= N_NODES) return;
    const int o = g_off[i] + g_bsum[i / SCAN_CHUNK];
    g_off[i] = o;
    g_cur[i] = o;
}

// ---------------- counting sort: scatter permuted sources -------------------------
__global__ void k_scatter(const int* __restrict__ ei) {
    const int e = blockIdx.x * blockDim.x + threadIdx.x;
    if (e >= E_TOT) return;
    const int is64 = g_flags[0];
    const int dst = edge_dst(ei, e, is64);
    const int src = edge_src(ei, e, is64);
    const int pos = atomicAdd(&g_cur[dst], 1);
    g_psrc[pos] = src;
}

// ---------------- fused aggregation: one warp per node (f32x2 inner loop) ---------
// Biases folded: sum_e a*(xl+bl) = acc + bl*sum_e a. Packed leakyrelu:
// lr(u) = 0.6*u + 0.4*|u|  (== u for u>0, 0.2u for u<0, one extra rounding).
__global__ void k_aggr(const float* __restrict__ att,
                       const float* __restrict__ bl,   const float* __restrict__ br,
                       const float* __restrict__ bias,
                       const float* __restrict__ Wlin, const float* __restrict__ blin,
                       const int* __restrict__ batch) {
    __shared__ __align__(16) float sW[OUT_CH * HID];   // sW[c*HID+k] = Wlin[k*16+c]
    const int t = threadIdx.x;                          // 256 threads = 8 warps
    for (int i = t; i < OUT_CH * HID; i += 256) {
        int c = i >> 7, k = i & 127;
        sW[i] = Wlin[k * OUT_CH + c];
    }
    __syncthreads();

    const int warp = t >> 5, l = t & 31;
    const int n = blockIdx.x * 8 + warp;
    if (n >= N_NODES) return;

    const int off = l * 4;
    const float4 xr4 = *reinterpret_cast<const float4*>(g_xr + (size_t)n * HID + off);
    const float4 at4 = *reinterpret_cast<const float4*>(att + off);
    const float4 bl4 = *reinterpret_cast<const float4*>(bl + off);
    const float4 br4 = *reinterpret_cast<const float4*>(br + off);
    const ull c01 = pk2(xr4.x + bl4.x + br4.x, xr4.y + bl4.y + br4.y);
    const ull c23 = pk2(xr4.z + bl4.z + br4.z, xr4.w + bl4.w + br4.w);
    const ull at01 = pk2(at4.x, at4.y);
    const ull at23 = pk2(at4.z, at4.w);
    const ull C06 = pk2(0.6f, 0.6f);
    const ull C04 = pk2(0.4f, 0.4f);

    ull acc01 = 0ULL, acc23 = 0ULL;
    float dsum = 0.f;

    const int p0 = g_off[n], p1 = g_off[n + 1];
    int i = p0;
    for (; i + 1 < p1; i += 2) {
        const int s0 = g_psrc[i];
        const int s1 = g_psrc[i + 1];
        const float4 xa = *reinterpret_cast<const float4*>(g_xl + (size_t)s0 * HID + off);
        const float4 xb = *reinterpret_cast<const float4*>(g_xl + (size_t)s1 * HID + off);
        const ull xa01 = pk2(xa.x, xa.y), xa23 = pk2(xa.z, xa.w);
        const ull xb01 = pk2(xb.x, xb.y), xb23 = pk2(xb.z, xb.w);

        ull u01 = add2(xa01, c01), u23 = add2(xa23, c23);
        ull v01 = fma2_(abs2(u01), C04, mul2(u01, C06));
        ull v23 = fma2_(abs2(u23), C04, mul2(u23, C06));
        ull sa2 = fma2_(v23, at23, mul2(v01, at01));

        ull w01 = add2(xb01, c01), w23 = add2(xb23, c23);
        ull y01 = fma2_(abs2(w01), C04, mul2(w01, C06));
        ull y23 = fma2_(abs2(w23), C04, mul2(w23, C06));
        ull sb2 = fma2_(y23, at23, mul2(y01, at01));

        float se, so;
        up2(sa2, se, so); float sa = se + so;
        up2(sb2, se, so); float sb = se + so;

        sa += __shfl_xor_sync(0xffffffffu, sa, 1);
        sa += __shfl_xor_sync(0xffffffffu, sa, 2);
        sb += __shfl_xor_sync(0xffffffffu, sb, 1);
        sb += __shfl_xor_sync(0xffffffffu, sb, 2);

        const float a0 = __expf(sa);
        const float a1 = __expf(sb);
        const ull a02 = pk2(a0, a0);
        const ull a12 = pk2(a1, a1);
        acc01 = fma2_(xa01, a02, acc01);
        acc23 = fma2_(xa23, a02, acc23);
        acc01 = fma2_(xb01, a12, acc01);
        acc23 = fma2_(xb23, a12, acc23);
        dsum += a0 + a1;
    }
    if (i < p1) {
        const int s0 = g_psrc[i];
        const float4 xa = *reinterpret_cast<const float4*>(g_xl + (size_t)s0 * HID + off);
        const ull xa01 = pk2(xa.x, xa.y), xa23 = pk2(xa.z, xa.w);
        ull u01 = add2(xa01, c01), u23 = add2(xa23, c23);
        ull v01 = fma2_(abs2(u01), C04, mul2(u01, C06));
        ull v23 = fma2_(abs2(u23), C04, mul2(u23, C06));
        ull sa2 = fma2_(v23, at23, mul2(v01, at01));
        float se, so;
        up2(sa2, se, so); float sa = se + so;
        sa += __shfl_xor_sync(0xffffffffu, sa, 1);
        sa += __shfl_xor_sync(0xffffffffu, sa, 2);
        const float a0 = __expf(sa);
        const ull a02 = pk2(a0, a0);
        acc01 = fma2_(xa01, a02, acc01);
        acc23 = fma2_(xa23, a02, acc23);
        dsum += a0;
    }

    const float4 xs4   = *reinterpret_cast<const float4*>(g_xres + (size_t)n * HID + off);
    const float4 bias4 = *reinterpret_cast<const float4*>(bias + off);
    const float inv = 1.f / dsum;
    float ax, ay, az, aw;
    up2(acc01, ax, ay);
    up2(acc23, az, aw);
    const float o0 = ax * inv + bl4.x + xs4.x + bias4.x;
    const float o1 = ay * inv + bl4.y + xs4.y + bias4.y;
    const float o2 = az * inv + bl4.z + xs4.z + bias4.z;
    const float o3 = aw * inv + bl4.w + xs4.w + bias4.w;

    float myv = 0.f;
#pragma unroll
    for (int c = 0; c < OUT_CH; c++) {
        const float4 w = *reinterpret_cast<const float4*>(sW + c * HID + off);
        float p = o0 * w.x + o1 * w.y + o2 * w.z + o3 * w.w;
        p += __shfl_xor_sync(0xffffffffu, p, 16);
        p += __shfl_xor_sync(0xffffffffu, p, 8);
        p += __shfl_xor_sync(0xffffffffu, p, 4);
        p += __shfl_xor_sync(0xffffffffu, p, 2);
        p += __shfl_xor_sync(0xffffffffu, p, 1);
        if (l == c) myv = p;
    }
    if (l < OUT_CH) {
        float hv = myv + blin[l];
        hv = hv > 0.f ? hv : (__expf(hv) - 1.f);         // ELU(alpha=1)
        const int is64 = g_flags[1];
        const int b = is64 ? batch[2 * n] : batch[n];
        atomicAdd(&g_gsum[b * OUT_CH + l], hv);
        if (l == 0) atomicAdd(&g_gcnt[b], 1.f);
    }
}

// ---------------- graph MLP: mean pool -> 16 -> 16 -> 32 -> 5 ---------------------
__global__ void k_mlp(const float* __restrict__ W1, const float* __restrict__ b1,
                      const float* __restrict__ W2, const float* __restrict__ b2,
                      const float* __restrict__ W3, const float* __restrict__ b3,
                      float* __restrict__ out) {
    const int g = blockIdx.x * blockDim.x + threadIdx.x;
    if (g >= N_GRAPHS) return;
    const float inv = 1.f / fmaxf(g_gcnt[g], 1.f);
    float v0[16];
#pragma unroll
    for (int c = 0; c < 16; c++) v0[c] = g_gsum[g * 16 + c] * inv;
    float v1[16];
#pragma unroll
    for (int j = 0; j < 16; j++) {
        float s = b1[j];
#pragma unroll
        for (int k = 0; k < 16; k++) s = fmaf(v0[k], W1[k * 16 + j], s);
        v1[j] = fmaxf(s, 0.f);
    }
    float v2[32];
#pragma unroll
    for (int j = 0; j < 32; j++) {
        float s = b2[j];
#pragma unroll
        for (int k = 0; k < 16; k++) s = fmaf(v1[k], W2[k * 32 + j], s);
        v2[j] = fmaxf(s, 0.f);
    }
#pragma unroll
    for (int j = 0; j < 5; j++) {
        float s = b3[j];
#pragma unroll
        for (int k = 0; k < 32; k++) s = fmaf(v2[k], W3[k * 5 + j], s);
        out[g * 5 + j] = s;
    }
}

// ---------------- launch ----------------------------------------------------------
// k_gemm stays in the 4th launch slot (ncu's bounded capture profiles launch 4).
extern "C" void kernel_launch(void* const* d_in, const int* in_sizes, int n_in,
                              void* d_out, int out_size) {
    const float* x     = (const float*)d_in[0];
    const int*   ei    = (const int*)  d_in[1];   // int32 or int64 (auto-detected)
    const int*   batch = (const int*)  d_in[2];
    const float* Wl    = (const float*)d_in[3];
    const float* bl    = (const float*)d_in[4];
    const float* Wr    = (const float*)d_in[5];
    const float* br    = (const float*)d_in[6];
    const float* att   = (const float*)d_in[7];
    const float* Wres  = (const float*)d_in[8];
    const float* bias  = (const float*)d_in[9];
    const float* Wlin  = (const float*)d_in[10];
    const float* blin  = (const float*)d_in[11];
    const float* W1    = (const float*)d_in[12];
    const float* b1    = (const float*)d_in[13];
    const float* W2    = (const float*)d_in[14];
    const float* b2    = (const float*)d_in[15];
    const float* W3    = (const float*)d_in[16];
    const float* b3    = (const float*)d_in[17];
    float* out = (float*)d_out;

    k_init<<<(N_NODES + 255) / 256, 256>>>(ei, batch);    // 1 (init + detect)
    k_hist<<<(E_TOT + 255) / 256, 256>>>(ei);             // 2
    k_scan1<<<SCAN_NB, SCAN_CHUNK>>>();                   // 3
    k_gemm<<<(N_NODES + 31) / 32, 256>>>(x, Wl, Wr, Wres);// 4  <- profiled slot
    k_scan2<<<1, 128>>>();                                // 5
    k_scan3<<<(N_NODES + 255) / 256, 256>>>();            // 6
    k_scatter<<<(E_TOT + 255) / 256, 256>>>(ei);          // 7
    k_aggr<<<(N_NODES + 7) / 8, 256>>>(att, bl, br, bias, Wlin, blin, batch); // 8
    k_mlp<<<(N_GRAPHS + 255) / 256, 256>>>(W1, b1, W2, b2, W3, b3, out);      // 9
}

// round 13
// speedup vs baseline: 1.2404x; 1.2404x over previous
#include <cuda_runtime.h>
#include <cstdint>

#define N_NODES 50000
#define N_EDGES 800000
#define E_TOT   850000          // edges + self loops
#define IN_CH   64
#define HEADS   8
#define OUT_CH  16
#define HID     128
#define N_GRAPHS 500
#define NEG_SLOPE 0.2f

#define SCAN_CHUNK 512
#define SCAN_NB    ((N_NODES + SCAN_CHUNK - 1) / SCAN_CHUNK)   // 98

typedef unsigned long long ull;

// ---------------- f32x2 packed helpers (sm_100+; ptxas never auto-emits FFMA2) ----
__device__ __forceinline__ ull pk2(float lo, float hi) {
    ull r; asm("mov.b64 %0, {%1, %2};" : "=l"(r) : "f"(lo), "f"(hi)); return r;
}
__device__ __forceinline__ void up2(ull v, float& lo, float& hi) {
    asm("mov.b64 {%0, %1}, %2;" : "=f"(lo), "=f"(hi) : "l"(v));
}
__device__ __forceinline__ ull add2(ull a, ull b) {
    ull d; asm("add.rn.f32x2 %0, %1, %2;" : "=l"(d) : "l"(a), "l"(b)); return d;
}
__device__ __forceinline__ ull mul2(ull a, ull b) {
    ull d; asm("mul.rn.f32x2 %0, %1, %2;" : "=l"(d) : "l"(a), "l"(b)); return d;
}
__device__ __forceinline__ ull fma2_(ull a, ull b, ull c) {
    ull d; asm("fma.rn.f32x2 %0, %1, %2, %3;" : "=l"(d) : "l"(a), "l"(b), "l"(c)); return d;
}
__device__ __forceinline__ ull abs2(ull a) {
    ull d; asm("and.b64 %0, %1, 0x7FFFFFFF7FFFFFFF;" : "=l"(d) : "l"(a)); return d;
}

// ---------------- scratch (static device globals) ---------------------------------
__device__ __align__(16) float g_xl[(size_t)N_NODES * HID];     // x@Wl (no bias)
__device__ __align__(16) float g_xr[(size_t)N_NODES * HID];     // x@Wr (no bias)
__device__ __align__(16) float g_xres[(size_t)N_NODES * HID];   // x@Wres (no bias)
__device__ int   g_cnt[N_NODES];          // in-degree histogram
__device__ int   g_off[N_NODES + 1];      // CSR row pointers
__device__ int   g_cur[N_NODES];          // scatter cursors
__device__ int   g_bsum[SCAN_NB];         // scan block sums
__device__ int   g_psrc[E_TOT];           // dst-sorted source ids
__device__ float g_gsum[N_GRAPHS * OUT_CH];
__device__ float g_gcnt[N_GRAPHS];
__device__ int   g_flags[2];   // [0]: edge_index is int64, [1]: batch is int64

// ---------------- init + dtype detection (merged) ---------------------------------
// int64 values < 2^31 stored little-endian -> every odd int32 word is 0.
__global__ void k_init(const int* __restrict__ ei, const int* __restrict__ batch) {
    const int i = blockIdx.x * blockDim.x + threadIdx.x;
    if (i == 0) {
        int acc = 0;
#pragma unroll 1
        for (int j = 0; j < 64; j++) acc |= ei[2 * j + 1];
        g_flags[0] = (acc == 0) ? 1 : 0;
        int acc2 = 0;
#pragma unroll 1
        for (int j = 0; j < 64; j++) acc2 |= batch[2001 + 2 * j];
        g_flags[1] = (acc2 == 0) ? 1 : 0;
    }
    if (i < N_NODES) g_cnt[i] = 0;
    if (i < N_GRAPHS * OUT_CH) g_gsum[i] = 0.f;
    if (i < N_GRAPHS) g_gcnt[i] = 0.f;
}

// ---------------- edge index helpers ----------------------------------------------
__device__ __forceinline__ int edge_dst(const int* __restrict__ ei, int e, int is64) {
    if (e >= N_EDGES) return e - N_EDGES;
    return is64 ? ei[2 * (N_EDGES + e)] : ei[N_EDGES + e];
}
__device__ __forceinline__ int edge_src(const int* __restrict__ ei, int e, int is64) {
    if (e >= N_EDGES) return e - N_EDGES;
    return is64 ? ei[2 * e] : ei[e];
}

// ---------------- counting sort: histogram ----------------------------------------
__global__ void k_hist(const int* __restrict__ ei) {
    const int e = blockIdx.x * blockDim.x + threadIdx.x;
    if (e >= E_TOT) return;
    const int dst = edge_dst(ei, e, g_flags[0]);
    atomicAdd(&g_cnt[dst], 1);
}

// ---------------- scan stage 1: per-chunk exclusive scan + chunk totals -----------
__global__ void k_scan1() {
    const int i = blockIdx.x * SCAN_CHUNK + threadIdx.x;
    const int lane = threadIdx.x & 31, wid = threadIdx.x >> 5;
    int c = (i < N_NODES) ? g_cnt[i] : 0;
    int v = c;
#pragma unroll
    for (int d = 1; d < 32; d <<= 1) {
        int t = __shfl_up_sync(0xffffffffu, v, d);
        if (lane >= d) v += t;
    }
    __shared__ int wsum[16];
    if (lane == 31) wsum[wid] = v;
    __syncthreads();
    if (wid == 0) {
        int w = (lane < 16) ? wsum[lane] : 0;
#pragma unroll
        for (int d = 1; d < 16; d <<= 1) {
            int t = __shfl_up_sync(0xffffffffu, w, d);
            if (lane >= d) w += t;
        }
        if (lane < 16) wsum[lane] = w;
    }
    __syncthreads();
    const int base = wid ? wsum[wid - 1] : 0;
    const int incl = v + base;
    if (i < N_NODES) g_off[i] = incl - c;     // chunk-local exclusive
    if (threadIdx.x == SCAN_CHUNK - 1) g_bsum[blockIdx.x] = incl;
}

// ---------------- fused node GEMMs (FFMA2, round-9 shape: best measured 61us) -----
// 128 threads = one output column each; 16 nodes (8 f32x2 node-pairs) per block.
// fma.rn.f32x2 rounds each lane identically to scalar fmaf -> bit-equal results.
__global__ void k_gemm(const float* __restrict__ x,
                       const float* __restrict__ Wl,
                       const float* __restrict__ Wr,
                       const float* __restrict__ Wres) {
    __shared__ __align__(16) float sx[IN_CH][16];   // [k][n]
    const int nb = blockIdx.x * 16;
    const int t  = threadIdx.x;            // 0..127 = output column
    for (int i = t; i < 16 * IN_CH; i += 128) {
        int n = i >> 6, k = i & 63;
        sx[k][n] = x[(size_t)(nb + n) * IN_CH + k];
    }
    __syncthreads();

    ull accl[8], accr[8], accs[8];
#pragma unroll
    for (int p = 0; p < 8; p++) { accl[p] = 0ULL; accr[p] = 0ULL; accs[p] = 0ULL; }

    const int c = t;
#pragma unroll 4
    for (int k = 0; k < IN_CH; k++) {
        const float wl = Wl[k * HID + c];
        const float wr = Wr[k * HID + c];
        const float ws = Wres[k * HID + c];
        const ull wl2 = pk2(wl, wl);
        const ull wr2 = pk2(wr, wr);
        const ull ws2 = pk2(ws, ws);
        const ull* xp = reinterpret_cast<const ull*>(sx[k]);   // 8 node-pairs (bcast)
#pragma unroll
        for (int p = 0; p < 8; p++) {
            const ull xv = xp[p];
            accl[p] = fma2_(xv, wl2, accl[p]);
            accr[p] = fma2_(xv, wr2, accr[p]);
            accs[p] = fma2_(xv, ws2, accs[p]);
        }
    }
#pragma unroll
    for (int p = 0; p < 8; p++) {
        float f0, f1;
        size_t o0 = (size_t)(nb + 2 * p) * HID + c;
        size_t o1 = (size_t)(nb + 2 * p + 1) * HID + c;
        up2(accl[p], f0, f1); g_xl[o0]   = f0; g_xl[o1]   = f1;
        up2(accr[p], f0, f1); g_xr[o0]   = f0; g_xr[o1]   = f1;
        up2(accs[p], f0, f1); g_xres[o0] = f0; g_xres[o1] = f1;
    }
}

// ---------------- scan stage 2: exclusive scan of chunk totals --------------------
__global__ void k_scan2() {
    const int lane = threadIdx.x & 31, wid = threadIdx.x >> 5;
    const int b = threadIdx.x;
    int c = (b < SCAN_NB) ? g_bsum[b] : 0;
    int v = c;
#pragma unroll
    for (int d = 1; d < 32; d <<= 1) {
        int t = __shfl_up_sync(0xffffffffu, v, d);
        if (lane >= d) v += t;
    }
    __shared__ int wsum[4];
    if (lane == 31) wsum[wid] = v;
    __syncthreads();
    int base = 0;
    for (int w = 0; w < wid; w++) base += wsum[w];
    if (b < SCAN_NB) g_bsum[b] = v + base - c;   // exclusive
    if (b == 0) g_off[N_NODES] = E_TOT;
}

// ---------------- scan stage 3: add chunk offsets, init cursors -------------------
__global__ void k_scan3() {
    const int i = blockIdx.x * blockDim.x + threadIdx.x;
    if (i >= N_NODES) return;
    const int o = g_off[i] + g_bsum[i / SCAN_CHUNK];
    g_off[i] = o;
    g_cur[i] = o;
}

// ---------------- counting sort: scatter permuted sources -------------------------
__global__ void k_scatter(const int* __restrict__ ei) {
    const int e = blockIdx.x * blockDim.x + threadIdx.x;
    if (e >= E_TOT) return;
    const int is64 = g_flags[0];
    const int dst = edge_dst(ei, e, is64);
    const int src = edge_src(ei, e, is64);
    const int pos = atomicAdd(&g_cur[dst], 1);
    g_psrc[pos] = src;
}

// ---------------- fused aggregation: one warp per node (f32x2 inner loop) ---------
// Biases folded: sum_e a*(xl+bl) = acc + bl*sum_e a. Packed leakyrelu:
// lr(u) = 0.6*u + 0.4*|u|  (== u for u>0, 0.2u for u<0, one extra rounding).
__global__ void k_aggr(const float* __restrict__ att,
                       const float* __restrict__ bl,   const float* __restrict__ br,
                       const float* __restrict__ bias,
                       const float* __restrict__ Wlin, const float* __restrict__ blin,
                       const int* __restrict__ batch) {
    __shared__ __align__(16) float sW[OUT_CH * HID];   // sW[c*HID+k] = Wlin[k*16+c]
    const int t = threadIdx.x;                          // 256 threads = 8 warps
    for (int i = t; i < OUT_CH * HID; i += 256) {
        int c = i >> 7, k = i & 127;
        sW[i] = Wlin[k * OUT_CH + c];
    }
    __syncthreads();

    const int warp = t >> 5, l = t & 31;
    const int n = blockIdx.x * 8 + warp;
    if (n >= N_NODES) return;

    const int off = l * 4;
    const float4 xr4 = *reinterpret_cast<const float4*>(g_xr + (size_t)n * HID + off);
    const float4 at4 = *reinterpret_cast<const float4*>(att + off);
    const float4 bl4 = *reinterpret_cast<const float4*>(bl + off);
    const float4 br4 = *reinterpret_cast<const float4*>(br + off);
    const ull c01 = pk2(xr4.x + bl4.x + br4.x, xr4.y + bl4.y + br4.y);
    const ull c23 = pk2(xr4.z + bl4.z + br4.z, xr4.w + bl4.w + br4.w);
    const ull at01 = pk2(at4.x, at4.y);
    const ull at23 = pk2(at4.z, at4.w);
    const ull C06 = pk2(0.6f, 0.6f);
    const ull C04 = pk2(0.4f, 0.4f);

    ull acc01 = 0ULL, acc23 = 0ULL;
    float dsum = 0.f;

    const int p0 = g_off[n], p1 = g_off[n + 1];
    int i = p0;
    for (; i + 1 < p1; i += 2) {
        const int s0 = g_psrc[i];
        const int s1 = g_psrc[i + 1];
        const float4 xa = *reinterpret_cast<const float4*>(g_xl + (size_t)s0 * HID + off);
        const float4 xb = *reinterpret_cast<const float4*>(g_xl + (size_t)s1 * HID + off);
        const ull xa01 = pk2(xa.x, xa.y), xa23 = pk2(xa.z, xa.w);
        const ull xb01 = pk2(xb.x, xb.y), xb23 = pk2(xb.z, xb.w);

        ull u01 = add2(xa01, c01), u23 = add2(xa23, c23);
        ull v01 = fma2_(abs2(u01), C04, mul2(u01, C06));
        ull v23 = fma2_(abs2(u23), C04, mul2(u23, C06));
        ull sa2 = fma2_(v23, at23, mul2(v01, at01));

        ull w01 = add2(xb01, c01), w23 = add2(xb23, c23);
        ull y01 = fma2_(abs2(w01), C04, mul2(w01, C06));
        ull y23 = fma2_(abs2(w23), C04, mul2(w23, C06));
        ull sb2 = fma2_(y23, at23, mul2(y01, at01));

        float se, so;
        up2(sa2, se, so); float sa = se + so;
        up2(sb2, se, so); float sb = se + so;

        sa += __shfl_xor_sync(0xffffffffu, sa, 1);
        sa += __shfl_xor_sync(0xffffffffu, sa, 2);
        sb += __shfl_xor_sync(0xffffffffu, sb, 1);
        sb += __shfl_xor_sync(0xffffffffu, sb, 2);

        const float a0 = __expf(sa);
        const float a1 = __expf(sb);
        const ull a02 = pk2(a0, a0);
        const ull a12 = pk2(a1, a1);
        acc01 = fma2_(xa01, a02, acc01);
        acc23 = fma2_(xa23, a02, acc23);
        acc01 = fma2_(xb01, a12, acc01);
        acc23 = fma2_(xb23, a12, acc23);
        dsum += a0 + a1;
    }
    if (i < p1) {
        const int s0 = g_psrc[i];
        const float4 xa = *reinterpret_cast<const float4*>(g_xl + (size_t)s0 * HID + off);
        const ull xa01 = pk2(xa.x, xa.y), xa23 = pk2(xa.z, xa.w);
        ull u01 = add2(xa01, c01), u23 = add2(xa23, c23);
        ull v01 = fma2_(abs2(u01), C04, mul2(u01, C06));
        ull v23 = fma2_(abs2(u23), C04, mul2(u23, C06));
        ull sa2 = fma2_(v23, at23, mul2(v01, at01));
        float se, so;
        up2(sa2, se, so); float sa = se + so;
        sa += __shfl_xor_sync(0xffffffffu, sa, 1);
        sa += __shfl_xor_sync(0xffffffffu, sa, 2);
        const float a0 = __expf(sa);
        const ull a02 = pk2(a0, a0);
        acc01 = fma2_(xa01, a02, acc01);
        acc23 = fma2_(xa23, a02, acc23);
        dsum += a0;
    }

    const float4 xs4   = *reinterpret_cast<const float4*>(g_xres + (size_t)n * HID + off);
    const float4 bias4 = *reinterpret_cast<const float4*>(bias + off);
    const float inv = 1.f / dsum;
    float ax, ay, az, aw;
    up2(acc01, ax, ay);
    up2(acc23, az, aw);
    const float o0 = ax * inv + bl4.x + xs4.x + bias4.x;
    const float o1 = ay * inv + bl4.y + xs4.y + bias4.y;
    const float o2 = az * inv + bl4.z + xs4.z + bias4.z;
    const float o3 = aw * inv + bl4.w + xs4.w + bias4.w;

    float myv = 0.f;
#pragma unroll
    for (int c = 0; c < OUT_CH; c++) {
        const float4 w = *reinterpret_cast<const float4*>(sW + c * HID + off);
        float p = o0 * w.x + o1 * w.y + o2 * w.z + o3 * w.w;
        p += __shfl_xor_sync(0xffffffffu, p, 16);
        p += __shfl_xor_sync(0xffffffffu, p, 8);
        p += __shfl_xor_sync(0xffffffffu, p, 4);
        p += __shfl_xor_sync(0xffffffffu, p, 2);
        p += __shfl_xor_sync(0xffffffffu, p, 1);
        if (l == c) myv = p;
    }
    if (l < OUT_CH) {
        float hv = myv + blin[l];
        hv = hv > 0.f ? hv : (__expf(hv) - 1.f);         // ELU(alpha=1)
        const int is64 = g_flags[1];
        const int b = is64 ? batch[2 * n] : batch[n];
        atomicAdd(&g_gsum[b * OUT_CH + l], hv);
        if (l == 0) atomicAdd(&g_gcnt[b], 1.f);
    }
}

// ---------------- graph MLP: mean pool -> 16 -> 16 -> 32 -> 5 ---------------------
__global__ void k_mlp(const float* __restrict__ W1, const float* __restrict__ b1,
                      const float* __restrict__ W2, const float* __restrict__ b2,
                      const float* __restrict__ W3, const float* __restrict__ b3,
                      float* __restrict__ out) {
    const int g = blockIdx.x * blockDim.x + threadIdx.x;
    if (g >= N_GRAPHS) return;
    const float inv = 1.f / fmaxf(g_gcnt[g], 1.f);
    float v0[16];
#pragma unroll
    for (int c = 0; c < 16; c++) v0[c] = g_gsum[g * 16 + c] * inv;
    float v1[16];
#pragma unroll
    for (int j = 0; j < 16; j++) {
        float s = b1[j];
#pragma unroll
        for (int k = 0; k < 16; k++) s = fmaf(v0[k], W1[k * 16 + j], s);
        v1[j] = fmaxf(s, 0.f);
    }
    float v2[32];
#pragma unroll
    for (int j = 0; j < 32; j++) {
        float s = b2[j];
#pragma unroll
        for (int k = 0; k < 16; k++) s = fmaf(v1[k], W2[k * 32 + j], s);
        v2[j] = fmaxf(s, 0.f);
    }
#pragma unroll
    for (int j = 0; j < 5; j++) {
        float s = b3[j];
#pragma unroll
        for (int k = 0; k < 32; k++) s = fmaf(v2[k], W3[k * 5 + j], s);
        out[g * 5 + j] = s;
    }
}

// ---------------- launch: fork GEMM onto a second stream, overlap with CSR build --
// The GEMM chain (k_gemm) and CSR chain (init/hist/scan/scatter) are independent;
// they only meet at k_aggr. Standard capture-legal event fork/join.
extern "C" void kernel_launch(void* const* d_in, const int* in_sizes, int n_in,
                              void* d_out, int out_size) {
    const float* x     = (const float*)d_in[0];
    const int*   ei    = (const int*)  d_in[1];   // int32 or int64 (auto-detected)
    const int*   batch = (const int*)  d_in[2];
    const float* Wl    = (const float*)d_in[3];
    const float* bl    = (const float*)d_in[4];
    const float* Wr    = (const float*)d_in[5];
    const float* br    = (const float*)d_in[6];
    const float* att   = (const float*)d_in[7];
    const float* Wres  = (const float*)d_in[8];
    const float* bias  = (const float*)d_in[9];
    const float* Wlin  = (const float*)d_in[10];
    const float* blin  = (const float*)d_in[11];
    const float* W1    = (const float*)d_in[12];
    const float* b1    = (const float*)d_in[13];
    const float* W2    = (const float*)d_in[14];
    const float* b2    = (const float*)d_in[15];
    const float* W3    = (const float*)d_in[16];
    const float* b3    = (const float*)d_in[17];
    float* out = (float*)d_out;

    // one-time host resource init (no device memory involved)
    static cudaStream_t s2 = nullptr;
    static cudaEvent_t evFork = nullptr, evJoin = nullptr;
    if (s2 == nullptr) {
        cudaStreamCreateWithFlags(&s2, cudaStreamNonBlocking);
        cudaEventCreateWithFlags(&evFork, cudaEventDisableTiming);
        cudaEventCreateWithFlags(&evJoin, cudaEventDisableTiming);
    }

    // fork point: s2 branches off the main (capture) stream at the very start
    cudaEventRecord(evFork, 0);
    cudaStreamWaitEvent(s2, evFork, 0);

    // CSR chain on main stream
    k_init<<<(N_NODES + 255) / 256, 256>>>(ei, batch);
    k_hist<<<(E_TOT + 255) / 256, 256>>>(ei);
    k_scan1<<<SCAN_NB, SCAN_CHUNK>>>();

    // GEMM chain on s2 (runs concurrent with the CSR chain from the fork point)
    k_gemm<<<(N_NODES + 15) / 16, 128, 0, s2>>>(x, Wl, Wr, Wres);
    cudaEventRecord(evJoin, s2);

    k_scan2<<<1, 128>>>();
    k_scan3<<<(N_NODES + 255) / 256, 256>>>();
    k_scatter<<<(E_TOT + 255) / 256, 256>>>(ei);

    // join: k_aggr needs both chains
    cudaStreamWaitEvent(0, evJoin, 0);
    k_aggr<<<(N_NODES + 7) / 8, 256>>>(att, bl, br, bias, Wlin, blin, batch);
    k_mlp<<<(N_GRAPHS + 255) / 256, 256>>>(W1, b1, W2, b2, W3, b3, out);
}